// round 16
// baseline (speedup 1.0000x reference)
#include <cuda_runtime.h>
#include <cuda_fp16.h>

#define NB     256
#define NPIX   (1024*1024)
#define NPIX4  (NPIX / 4)
#define NBATCH 16
#define TPB    256
#define IT     4                         // 4 float4 (16 px) per thread
#define CPI    (NPIX4 / (TPB * IT))      // 256 CTAs per image
#define NCTA   (CPI * NBATCH)            // 4096 total

// Scratch (no allocations). Every flag/counter is consumed-and-reset within
// one replay, so graph replays are deterministic.
__device__ int   g_histo[NBATCH][NB];
__device__ int   g_count[NBATCH];
__device__ int   g_ready[NBATCH];
__device__ int   g_done[NBATCH];
__device__ float g_lut[NBATCH][NB];
__device__ float g_step[NBATCH];

__device__ __forceinline__ float clip01(float x) {
    return fminf(fmaxf(x, 0.0f), 1.0f);
}

__device__ __forceinline__ unsigned int pack_h2(float a, float b) {
    __half2 h = __floats2half2_rn(a, b);
    return ((unsigned int)__half_as_ushort(__high2half(h)) << 16) |
           (unsigned int)__half_as_ushort(__low2half(h));
}

__device__ __forceinline__ float2 unpack_h2(unsigned int w) {
    float lo = __half2float(__ushort_as_half((unsigned short)(w & 0xffffu)));
    float hi = __half2float(__ushort_as_half((unsigned short)(w >> 16)));
    return make_float2(lo, hi);
}

// Single fused kernel: hist -> (ticket) LUT -> spin -> map from registers.
__global__ void __launch_bounds__(TPB, 4)
eq_kernel(const float* __restrict__ img, float* __restrict__ out) {
    __shared__ int   sh[NB];
    __shared__ float h[NB];
    __shared__ float s[NB];
    __shared__ float lutS[NB];
    __shared__ float stepS;
    __shared__ int   lastIdx;
    __shared__ int   isLast;

    const int bid = blockIdx.x;
    const int b   = bid / CPI;            // image-major linear order
    const int bx  = bid % CPI;

    for (int i = threadIdx.x; i < NB; i += TPB) sh[i] = 0;
    __syncthreads();

    const size_t base = (size_t)b * 3 * NPIX;
    const float4* __restrict__ R  = (const float4*)(img + base);
    const float4* __restrict__ Gc = (const float4*)(img + base + NPIX);
    const float4* __restrict__ B  = (const float4*)(img + base + 2 * NPIX);

    const int tile = bx * (TPB * IT);
    const float scale = (float)(256.0 / 255.0);   // NUM_BINS / 255.0 in f32

    // ---- Phase 1: histogram + pack YUV into registers -------------------
    unsigned int gidx[IT], upk[IT], vpk[IT];

    #pragma unroll
    for (int k = 0; k < IT; k++) {
        int i = tile + k * TPB + threadIdx.x;
        float4 r4 = __ldcs(R + i);        // only touch of the input
        float4 g4 = __ldcs(Gc + i);
        float4 b4 = __ldcs(B + i);

        unsigned int gx = 0u;
        float uf[4], vf[4];
        #pragma unroll
        for (int c = 0; c < 4; c++) {
            float r  = clip01(((const float*)&r4)[c]);
            float g  = clip01(((const float*)&g4)[c]);
            float bb = clip01(((const float*)&b4)[c]);
            float y = 0.299f * r + 0.587f * g + 0.114f * bb;
            uf[c]   = -0.147f * r - 0.289f * g + 0.436f * bb;
            vf[c]   =  0.615f * r - 0.515f * g - 0.100f * bb;

            float t = y * 255.0f;
            int bin = (int)floorf(t * scale);
            bin = min(max(bin, 0), NB - 1);
            atomicAdd(&sh[bin], 1);

            int gi = min(max((int)t, 0), NB - 1);   // exact reference gather
            gx |= (unsigned int)gi << (8 * c);
        }
        gidx[k] = gx;
        upk[k]  = pack_h2(uf[0], uf[1]);
        vpk[k]  = pack_h2(vf[0], vf[1]);
        // pack the other two lanes into the high half via a second word:
        // store pairs (0,1) and (2,3) in alternating registers
        gx = pack_h2(uf[2], uf[3]);
        unsigned int vx = pack_h2(vf[2], vf[3]);
        upk[k] = (upk[k] & 0xffffffffu);  // keep
        // we need 2 words per 4 px for u and v: use separate arrays
        // (handled below by u2/v2 arrays)
        (void)gx; (void)vx;
        // NOTE: replaced by full arrays below.
    }

    // Full-width u/v registers (2 words per iteration -> 8 words each)
    // Recompute cleanly to keep indexing simple (compiler folds duplicates).
    unsigned int u2[2 * IT], v2[2 * IT];
    #pragma unroll
    for (int k = 0; k < IT; k++) {
        int i = tile + k * TPB + threadIdx.x;
        float4 r4 = R[i];                 // L1-resident: just re-read
        float4 g4 = Gc[i];
        float4 b4 = B[i];
        float uf[4], vf[4];
        #pragma unroll
        for (int c = 0; c < 4; c++) {
            float r  = clip01(((const float*)&r4)[c]);
            float g  = clip01(((const float*)&g4)[c]);
            float bb = clip01(((const float*)&b4)[c]);
            uf[c] = -0.147f * r - 0.289f * g + 0.436f * bb;
            vf[c] =  0.615f * r - 0.515f * g - 0.100f * bb;
        }
        u2[2 * k]     = pack_h2(uf[0], uf[1]);
        u2[2 * k + 1] = pack_h2(uf[2], uf[3]);
        v2[2 * k]     = pack_h2(vf[0], vf[1]);
        v2[2 * k + 1] = pack_h2(vf[2], vf[3]);
    }
    __syncthreads();

    // ---- Publish histogram + ticket -------------------------------------
    {
        int t = threadIdx.x;              // TPB == NB
        if (sh[t]) atomicAdd(&g_histo[b][t], sh[t]);
    }
    __threadfence();

    if (threadIdx.x == 0) {
        isLast = (atomicAdd(&g_count[b], 1) == (CPI - 1));
        lastIdx = 0;
    }
    __syncthreads();

    if (isLast) {
        // ---- Last-arriving CTA: compute LUT, publish, raise flag --------
        const int t = threadIdx.x;
        float hv = (float)__ldcg(&g_histo[b][t]);
        g_histo[b][t] = 0;                // reset for next replay
        h[t] = hv;
        s[t] = hv;
        __syncthreads();

        for (int off = 1; off < NB; off <<= 1) {
            float add = (t >= off) ? s[t - off] : 0.0f;
            __syncthreads();
            s[t] += add;
            __syncthreads();
        }

        if (hv > 0.0f) atomicMax(&lastIdx, t);
        __syncthreads();

        float total    = s[NB - 1];
        float last_val = h[lastIdx];
        float step     = floorf(__fdiv_rn(total - last_val, 255.0f));
        float safe     = fmaxf(step, 1.0f);
        float half     = floorf(__fdiv_rn(step, 2.0f));

        float lv;
        if (t == 0) {
            lv = 0.0f;
        } else {
            lv = floorf(__fdiv_rn(s[t - 1] + half, safe));
            lv = fminf(fmaxf(lv, 0.0f), 255.0f);
        }
        g_lut[b][t] = lv;
        if (t == 0) {
            g_step[b]  = step;
            g_count[b] = 0;               // reset ticket for next replay
        }
        __threadfence();
        __syncthreads();
        if (t == 0) atomicExch(&g_ready[b], 1);
    }

    // ---- Spin until this image's LUT is published -----------------------
    if (threadIdx.x == 0) {
        while (atomicAdd(&g_ready[b], 0) == 0) __nanosleep(200);
    }
    __syncthreads();

    // Load LUT into shared (L1-bypass: another SM wrote it).
    lutS[threadIdx.x] = __ldcg(&g_lut[b][threadIdx.x]);
    if (threadIdx.x == 0) stepS = __ldcg(&g_step[b]);
    __syncthreads();

    // Done-ticket: safe to count now — this CTA's global LUT reads are done.
    if (threadIdx.x == 0) {
        if (atomicAdd(&g_done[b], 1) == (CPI - 1)) {
            g_done[b]  = 0;               // reset for next replay
            atomicExch(&g_ready[b], 0);
        }
    }

    const bool identity = (stepS == 0.0f);  // dead for 1M-px random images

    // ---- Phase 2: map from registers, write output ----------------------
    float4* __restrict__ Ro = (float4*)(out + base);
    float4* __restrict__ Go = (float4*)(out + base + NPIX);
    float4* __restrict__ Bo = (float4*)(out + base + 2 * NPIX);

    const float inv255 = 1.0f / 255.0f;

    #pragma unroll
    for (int k = 0; k < IT; k++) {
        int i = tile + k * TPB + threadIdx.x;
        float2 u01 = unpack_h2(u2[2 * k]);
        float2 u23 = unpack_h2(u2[2 * k + 1]);
        float2 v01 = unpack_h2(v2[2 * k]);
        float2 v23 = unpack_h2(v2[2 * k + 1]);
        float uf[4] = {u01.x, u01.y, u23.x, u23.y};
        float vf[4] = {v01.x, v01.y, v23.x, v23.y};

        float4 ro, go, bo;
        #pragma unroll
        for (int c = 0; c < 4; c++) {
            int gi = (gidx[k] >> (8 * c)) & 255;
            float outv = identity ? ((float)gi + 0.5f) : lutS[gi];
            float ye = outv * inv255;
            float u = uf[c], v = vf[c];
            ((float*)&ro)[c] = ye + 1.14f * v;
            ((float*)&go)[c] = ye - 0.396f * u - 0.581f * v;
            ((float*)&bo)[c] = ye + 2.029f * u;
        }
        __stcs(Ro + i, ro);
        __stcs(Go + i, go);
        __stcs(Bo + i, bo);
    }
}

extern "C" void kernel_launch(void* const* d_in, const int* in_sizes, int n_in,
                              void* d_out, int out_size) {
    const float* img = (const float*)d_in[0];
    float*       out = (float*)d_out;
    eq_kernel<<<NCTA, TPB>>>(img, out);
}

// round 17
// speedup vs baseline: 1.3632x; 1.3632x over previous
#include <cuda_runtime.h>

#define NB     256
#define NPIX   (1024*1024)
#define NPIX4  (NPIX / 4)
#define NBATCH 16
#define TPB    256
#define IT_H   4                  // hist: 4 float4 per thread (16 px)
#define IT_M   4                  // map : 4 uint4 items per thread (16 px)
#define BLKX_H (NPIX4 / (TPB * IT_H))   // 256 blocks per image
#define BLKX_M (NPIX4 / (TPB * IT_M))   // 256 blocks per image

// 12-bit fixed-point ranges for u, v (exact value ranges of the transform).
#define U_OFF  0.436f
#define U_ENC  (4095.0f / 0.872f)
#define U_DEC  (0.872f / 4095.0f)
#define V_OFF  0.615f
#define V_ENC  (4095.0f / 1.230f)
#define V_DEC  (1.230f / 4095.0f)

// Scratch (no allocations). Histo/ticket consumed-and-reset per replay;
// staging fully overwritten each replay before being read.
__device__ int   g_histo[NBATCH][NB];
__device__ int   g_count[NBATCH];
__device__ float g_lut[NBATCH][NB];
__device__ float g_step[NBATCH];

// Compacted YUV staging: one u32 per pixel = gi(8) | qu(12) | qv(12).
// 64 MB total — L2-resident between hist and map.
__device__ uint4 g_pack[NBATCH * NPIX4];          // 64 MB

__device__ __forceinline__ float clip01(float x) {
    return fminf(fmaxf(x, 0.0f), 1.0f);
}

// Pass 1: the ONLY reader of the RGB input (__ldcs: last touch). Builds the
// per-image Y histogram, stages packed {gi, qu, qv}, and the last-arriving
// block computes the LUT (ticket pattern).
__global__ void hist_kernel(const float* __restrict__ img) {
    __shared__ int   sh[NB];
    __shared__ float h[NB];
    __shared__ float s[NB];
    __shared__ int   lastIdx;
    __shared__ int   isLast;

    for (int i = threadIdx.x; i < NB; i += TPB) sh[i] = 0;
    __syncthreads();

    const int b = blockIdx.y;
    const size_t base = (size_t)b * 3 * NPIX;
    const float4* __restrict__ R  = (const float4*)(img + base);
    const float4* __restrict__ Gc = (const float4*)(img + base + NPIX);
    const float4* __restrict__ B  = (const float4*)(img + base + 2 * NPIX);

    uint4* __restrict__ P = g_pack + (size_t)b * NPIX4;

    const int tile = blockIdx.x * (TPB * IT_H);
    const float scale = (float)(256.0 / 255.0);   // NUM_BINS / 255.0 in f32

    #pragma unroll
    for (int k = 0; k < IT_H; k++) {
        int i = tile + k * TPB + threadIdx.x;
        float4 r4 = __ldcs(R + i);
        float4 g4 = __ldcs(Gc + i);
        float4 b4 = __ldcs(B + i);

        unsigned int w[4];
        #pragma unroll
        for (int c = 0; c < 4; c++) {
            float r  = clip01(((const float*)&r4)[c]);
            float g  = clip01(((const float*)&g4)[c]);
            float bb = clip01(((const float*)&b4)[c]);
            float y = 0.299f * r + 0.587f * g + 0.114f * bb;
            float u = -0.147f * r - 0.289f * g + 0.436f * bb;
            float v =  0.615f * r - 0.515f * g - 0.100f * bb;

            float t = y * 255.0f;
            int bin = (int)floorf(t * scale);
            bin = min(max(bin, 0), NB - 1);
            atomicAdd(&sh[bin], 1);

            int gi = min(max((int)t, 0), NB - 1);   // exact reference gather
            int qu = min(max(__float2int_rn((u + U_OFF) * U_ENC), 0), 4095);
            int qv = min(max(__float2int_rn((v + V_OFF) * V_ENC), 0), 4095);
            w[c] = (unsigned int)gi | ((unsigned int)qu << 8)
                 | ((unsigned int)qv << 20);
        }
        P[i] = make_uint4(w[0], w[1], w[2], w[3]);
    }
    __syncthreads();

    {   // publish histogram (TPB == NB: one bin per thread)
        int t = threadIdx.x;
        if (sh[t]) atomicAdd(&g_histo[b][t], sh[t]);
    }
    __threadfence();

    if (threadIdx.x == 0) {
        isLast = (atomicAdd(&g_count[b], 1) == (BLKX_H - 1));
        lastIdx = 0;
    }
    __syncthreads();
    if (!isLast) return;

    // ---- Last-arriving block: compute LUT for image b, reset counters ----
    const int t = threadIdx.x;
    float hv = (float)__ldcg(&g_histo[b][t]);   // other SMs wrote: bypass L1
    g_histo[b][t] = 0;                          // reset for next replay
    h[t] = hv;
    s[t] = hv;
    __syncthreads();

    // Inclusive Hillis-Steele scan (fp32 exact: counts < 2^24).
    for (int off = 1; off < NB; off <<= 1) {
        float add = (t >= off) ? s[t - off] : 0.0f;
        __syncthreads();
        s[t] += add;
        __syncthreads();
    }

    if (hv > 0.0f) atomicMax(&lastIdx, t);
    __syncthreads();

    float total    = s[NB - 1];
    float last_val = h[lastIdx];
    float step     = floorf(__fdiv_rn(total - last_val, 255.0f));
    float safe     = fmaxf(step, 1.0f);
    float half     = floorf(__fdiv_rn(step, 2.0f));

    float lv;
    if (t == 0) {
        lv = 0.0f;
    } else {
        lv = floorf(__fdiv_rn(s[t - 1] + half, safe));
        lv = fminf(fmaxf(lv, 0.0f), 255.0f);
    }
    g_lut[b][t] = lv;
    if (t == 0) {
        g_step[b]  = step;
        g_count[b] = 0;                         // reset ticket for next replay
    }
}

// Pass 2: consumes ONLY the 64 MB staging (palindrome image order: most
// recently written first; __ldcs = last touch) and writes the RGB output
// (__stcs: never re-read).
__global__ void map_kernel(float* __restrict__ out) {
    __shared__ float lut[NB];
    __shared__ float stepv;

    const int b = NBATCH - 1 - blockIdx.y;      // reverse image order
    for (int i = threadIdx.x; i < NB; i += TPB) lut[i] = g_lut[b][i];
    if (threadIdx.x == 0) stepv = g_step[b];
    __syncthreads();

    const bool identity = (stepv == 0.0f);      // dead for 1M-px images

    const size_t base = (size_t)b * 3 * NPIX;
    float4* __restrict__ Ro = (float4*)(out + base);
    float4* __restrict__ Go = (float4*)(out + base + NPIX);
    float4* __restrict__ Bo = (float4*)(out + base + 2 * NPIX);

    const uint4* __restrict__ P = g_pack + (size_t)b * NPIX4;

    const int tile = blockIdx.x * (TPB * IT_M);
    const float inv255 = 1.0f / 255.0f;

    #pragma unroll
    for (int k = 0; k < IT_M; k++) {
        int i = tile + k * TPB + threadIdx.x;
        uint4 pw = __ldcs(P + i);
        const unsigned int w[4] = {pw.x, pw.y, pw.z, pw.w};

        float4 ro, go, bo;
        #pragma unroll
        for (int c = 0; c < 4; c++) {
            unsigned int ww = w[c];
            int gi = (int)(ww & 255u);
            float u = (float)(int)((ww >> 8) & 4095u) * U_DEC - U_OFF;
            float v = (float)(int)(ww >> 20) * V_DEC - V_OFF;

            float outv = identity ? ((float)gi + 0.5f) : lut[gi];
            float ye = outv * inv255;

            ((float*)&ro)[c] = ye + 1.14f * v;
            ((float*)&go)[c] = ye - 0.396f * u - 0.581f * v;
            ((float*)&bo)[c] = ye + 2.029f * u;
        }
        __stcs(Ro + i, ro);
        __stcs(Go + i, go);
        __stcs(Bo + i, bo);
    }
}

extern "C" void kernel_launch(void* const* d_in, const int* in_sizes, int n_in,
                              void* d_out, int out_size) {
    const float* img = (const float*)d_in[0];
    float*       out = (float*)d_out;

    dim3 gh(BLKX_H, NBATCH);
    dim3 gm(BLKX_M, NBATCH);
    hist_kernel<<<gh, TPB>>>(img);
    map_kernel<<<gm, TPB>>>(out);
}